// round 6
// baseline (speedup 1.0000x reference)
#include <cuda_runtime.h>
#include <cuda_bf16.h>
#include <math.h>
#include <stdint.h>

// Problem constants
#define B_   2
#define S_   1024
#define D_   1024
#define E_   8
#define KTOP 2
#define FF_  2048
#define T_   (B_ * S_)
#define OUT_MAIN (T_ * D_)
#define OUT_FULL (OUT_MAIN + T_*E_ + T_*KTOP + T_*KTOP)

// GEMM tiling: 128x128x64 stages, 512 threads / 16 warps (4x4), warp tile 32x32
#define BM 128
#define BN 128
#define BK 64
// smem stage: A_hi 16K | A_lo 16K | B_hi 16K | B_lo 16K  (128 rows x 64 bf16 = 128B/row)
#define AH_OFF 0
#define AL_OFF 16384
#define BH_OFF 32768
#define BL_OFF 49152
#define STAGE  65536
#define SOFF_BUF 1024          // toks [0,512), wts [512,1024)
#define SMEM_TOTAL (SOFF_BUF + 2 * STAGE)   // 132096

// Device scratch
__device__ int   g_cnt[E_];
__device__ int   g_tok[E_ * T_];
__device__ float g_wt [E_ * T_];
__device__ __nv_bfloat16 g_h_hi[(size_t)E_ * T_ * FF_];
__device__ __nv_bfloat16 g_h_lo[(size_t)E_ * T_ * FF_];

// ---------------------------------------------------------------------------
__device__ __forceinline__ uint32_t smem_u32(const void* p) {
    uint32_t a;
    asm("{ .reg .u64 t; cvta.to.shared.u64 t, %1; cvt.u32.u64 %0, t; }"
        : "=r"(a) : "l"(p));
    return a;
}

// swizzled byte offset inside a [rows][64 bf16] tile (128B rows, 8 x 16B chunks)
__device__ __forceinline__ uint32_t swz(int r, int c) {
    return (uint32_t)(r * 128 + ((c ^ (r & 7)) << 4));
}

__device__ __forceinline__ void ldsm_x4(uint32_t addr, uint32_t r[4]) {
    asm volatile("ldmatrix.sync.aligned.m8n8.x4.shared.b16 {%0,%1,%2,%3}, [%4];"
                 : "=r"(r[0]), "=r"(r[1]), "=r"(r[2]), "=r"(r[3]) : "r"(addr));
}

__device__ __forceinline__ void mma_bf16(float c[4], const uint32_t a[4],
                                         uint32_t b0, uint32_t b1) {
    asm volatile("mma.sync.aligned.m16n8k16.row.col.f32.bf16.bf16.f32 "
                 "{%0,%1,%2,%3}, {%4,%5,%6,%7}, {%8,%9}, {%0,%1,%2,%3};"
                 : "+f"(c[0]), "+f"(c[1]), "+f"(c[2]), "+f"(c[3])
                 : "r"(a[0]), "r"(a[1]), "r"(a[2]), "r"(a[3]),
                   "r"(b0), "r"(b1));
}

__device__ __forceinline__ uint32_t pack_hi(float a, float b, float& ra, float& rb) {
    __nv_bfloat162 h = __float22bfloat162_rn(make_float2(a, b));
    ra = a - __bfloat162float(h.x);
    rb = b - __bfloat162float(h.y);
    return *reinterpret_cast<uint32_t*>(&h);
}
__device__ __forceinline__ uint32_t pack_bf2(float a, float b) {
    __nv_bfloat162 h = __float22bfloat162_rn(make_float2(a, b));
    return *reinterpret_cast<uint32_t*>(&h);
}

__device__ __forceinline__ void load16f(float4 f[4], const float* p) {
    if (p) {
        f[0] = *(const float4*)p;        f[1] = *(const float4*)(p + 4);
        f[2] = *(const float4*)(p + 8);  f[3] = *(const float4*)(p + 12);
    } else {
        f[0] = f[1] = f[2] = f[3] = make_float4(0.f, 0.f, 0.f, 0.f);
    }
}

// split 16 fp32 -> 2x16B hi chunks + 2x16B lo chunks at offA/offB
__device__ __forceinline__ void split16(char* hi, char* lo,
                                        uint32_t offA, uint32_t offB,
                                        const float4 f[4]) {
    float ra, rb;
    uint4 H, L;
    H.x = pack_hi(f[0].x, f[0].y, ra, rb); L.x = pack_bf2(ra, rb);
    H.y = pack_hi(f[0].z, f[0].w, ra, rb); L.y = pack_bf2(ra, rb);
    H.z = pack_hi(f[1].x, f[1].y, ra, rb); L.z = pack_bf2(ra, rb);
    H.w = pack_hi(f[1].z, f[1].w, ra, rb); L.w = pack_bf2(ra, rb);
    *(uint4*)(hi + offA) = H; *(uint4*)(lo + offA) = L;
    H.x = pack_hi(f[2].x, f[2].y, ra, rb); L.x = pack_bf2(ra, rb);
    H.y = pack_hi(f[2].z, f[2].w, ra, rb); L.y = pack_bf2(ra, rb);
    H.z = pack_hi(f[3].x, f[3].y, ra, rb); L.z = pack_bf2(ra, rb);
    H.w = pack_hi(f[3].z, f[3].w, ra, rb); L.w = pack_bf2(ra, rb);
    *(uint4*)(hi + offB) = H; *(uint4*)(lo + offB) = L;
}

// ---------------------------------------------------------------------------
__global__ void zero_kernel(float* __restrict__ out, int n) {
    int i = blockIdx.x * blockDim.x + threadIdx.x;
    if (i < n) out[i] = 0.0f;
    if (blockIdx.x == 0 && threadIdx.x < E_) g_cnt[threadIdx.x] = 0;
}

// ---------------------------------------------------------------------------
__global__ void router_kernel(const float* __restrict__ x,
                              const float* __restrict__ rw,
                              float* __restrict__ out, int out_size) {
    const int t = blockIdx.x;
    __shared__ float xs[D_];
    __shared__ float logits[E_];

    for (int i = threadIdx.x; i < D_; i += blockDim.x)
        xs[i] = x[(size_t)t * D_ + i];
    __syncthreads();

    const int w = threadIdx.x >> 5;
    const int lane = threadIdx.x & 31;
    float s = 0.0f;
    const float* rwe = rw + (size_t)w * D_;
    for (int k = lane; k < D_; k += 32) s += xs[k] * rwe[k];
    #pragma unroll
    for (int o = 16; o; o >>= 1) s += __shfl_xor_sync(0xffffffffu, s, o);
    if (lane == 0) logits[w] = s;
    __syncthreads();

    if (threadIdx.x == 0) {
        float mx = logits[0];
        #pragma unroll
        for (int e = 1; e < E_; e++) mx = fmaxf(mx, logits[e]);
        float p[E_]; float sum = 0.0f;
        #pragma unroll
        for (int e = 0; e < E_; e++) { p[e] = expf(logits[e] - mx); sum += p[e]; }
        float inv = 1.0f / sum;
        #pragma unroll
        for (int e = 0; e < E_; e++) p[e] *= inv;

        int i0 = 0;
        #pragma unroll
        for (int e = 1; e < E_; e++) if (p[e] > p[i0]) i0 = e;
        int i1 = (i0 == 0) ? 1 : 0;
        #pragma unroll
        for (int e = 0; e < E_; e++) if (e != i0 && p[e] > p[i1]) i1 = e;

        float w0 = p[i0], w1 = p[i1];
        float rinv = 1.0f / (w0 + w1);
        w0 *= rinv; w1 *= rinv;

        int s0 = atomicAdd(&g_cnt[i0], 1);
        g_tok[i0 * T_ + s0] = t; g_wt[i0 * T_ + s0] = w0;
        int s1 = atomicAdd(&g_cnt[i1], 1);
        g_tok[i1 * T_ + s1] = t; g_wt[i1 * T_ + s1] = w1;

        if (out_size >= OUT_FULL) {
            float* probs = out + OUT_MAIN;
            float* idxs  = out + OUT_MAIN + T_ * E_;
            float* wts   = out + OUT_MAIN + T_ * E_ + T_ * KTOP;
            #pragma unroll
            for (int e = 0; e < E_; e++) probs[t * E_ + e] = p[e];
            idxs[t * KTOP + 0] = (float)i0;
            idxs[t * KTOP + 1] = (float)i1;
            wts [t * KTOP + 0] = w0;
            wts [t * KTOP + 1] = w1;
        }
    }
}

// ---------------------------------------------------------------------------
// one pipeline stage's MMA phase: warp tile 32x32, pass-major ordering so
// same-accumulator MMAs are 8 instructions apart (no RAW serialization).
// ---------------------------------------------------------------------------
__device__ __forceinline__ void mma_stage(uint32_t base, int a_r, int a_c,
                                          int b_r, int b_c,
                                          float acc[2][4][4]) {
    #pragma unroll
    for (int ks = 0; ks < 4; ks++) {
        uint32_t ah[2][4], al[2][4], bh[2][4], bl[2][4];
        #pragma unroll
        for (int mi = 0; mi < 2; mi++) {
            uint32_t off = swz(a_r + mi * 16, ks * 2 + a_c);
            ldsm_x4(base + AH_OFF + off, ah[mi]);
            ldsm_x4(base + AL_OFF + off, al[mi]);
        }
        #pragma unroll
        for (int nj = 0; nj < 2; nj++) {
            uint32_t off = swz(b_r + nj * 16, ks * 2 + b_c);
            ldsm_x4(base + BH_OFF + off, bh[nj]);
            ldsm_x4(base + BL_OFF + off, bl[nj]);
        }
        // pass 1: hi * hi
        #pragma unroll
        for (int mi = 0; mi < 2; mi++)
            #pragma unroll
            for (int nj = 0; nj < 2; nj++)
                #pragma unroll
                for (int h = 0; h < 2; h++)
                    mma_bf16(acc[mi][nj*2+h], ah[mi], bh[nj][h*2], bh[nj][h*2+1]);
        // pass 2: hi * lo
        #pragma unroll
        for (int mi = 0; mi < 2; mi++)
            #pragma unroll
            for (int nj = 0; nj < 2; nj++)
                #pragma unroll
                for (int h = 0; h < 2; h++)
                    mma_bf16(acc[mi][nj*2+h], ah[mi], bl[nj][h*2], bl[nj][h*2+1]);
        // pass 3: lo * hi
        #pragma unroll
        for (int mi = 0; mi < 2; mi++)
            #pragma unroll
            for (int nj = 0; nj < 2; nj++)
                #pragma unroll
                for (int h = 0; h < 2; h++)
                    mma_bf16(acc[mi][nj*2+h], al[mi], bh[nj][h*2], bh[nj][h*2+1]);
    }
}

// ---------------------------------------------------------------------------
// GEMM1: H[s,n] = silu( X[tok(s),:] . W1[e,n,:] ), H stored split bf16 hi/lo
// ---------------------------------------------------------------------------
__global__ void __launch_bounds__(512, 1)
expert_gemm1_mma(const float* __restrict__ x, const float* __restrict__ w1) {
    extern __shared__ char smem[];
    const int e = blockIdx.z;
    const int n_e = g_cnt[e];
    const int row0 = blockIdx.y * BM;
    if (row0 >= n_e) return;
    const int col0 = blockIdx.x * BN;
    const int tid = threadIdx.x, wid = tid >> 5, lane = tid & 31;

    int* toks = (int*)smem;
    if (tid < BM) {
        int r = row0 + tid;
        toks[tid] = (r < n_e) ? g_tok[e * T_ + r] : -1;
    }
    __syncthreads();
    const uint32_t sb = smem_u32(smem);

    // loader role: 4 threads per row, 16 fp32 each
    const int lr = tid >> 2, q = tid & 3;
    const int tok = toks[lr];
    const float* aptr = (tok >= 0) ? x + (size_t)tok * D_ + q * 16 : nullptr;
    const float* bptr = w1 + (size_t)e * FF_ * D_ + (size_t)(col0 + lr) * D_ + q * 16;
    const uint32_t offA = swz(lr, q * 2), offB = swz(lr, q * 2 + 1);

    // mma role: 4x4 warp grid, warp tile 32x32
    const int warp_m = wid & 3, warp_n = wid >> 2;
    const int a_r = warp_m * 32 + (lane & 15);
    const int a_c = lane >> 4;
    const int b_r = warp_n * 32 + (lane & 7) + ((lane >> 4) & 1) * 8;
    const int b_c = (lane >> 3) & 1;

    float acc[2][4][4] = {};
    float4 fa[4], fb[4];
    load16f(fa, aptr);
    load16f(fb, bptr);

    const int S = D_ / BK;
    #pragma unroll 1
    for (int s = 0; s < S; s++) {
        char* bufc = smem + SOFF_BUF + (s & 1) * STAGE;
        split16(bufc + AH_OFF, bufc + AL_OFF, offA, offB, fa);
        split16(bufc + BH_OFF, bufc + BL_OFF, offA, offB, fb);
        __syncthreads();
        if (s + 1 < S) {
            load16f(fa, aptr ? aptr + (s + 1) * BK : nullptr);
            load16f(fb, bptr + (s + 1) * BK);
        }
        mma_stage(sb + SOFF_BUF + (s & 1) * STAGE, a_r, a_c, b_r, b_c, acc);
    }

    // epilogue: silu -> split bf16 -> g_h
    const int g = lane >> 2, tq = lane & 3;
    #pragma unroll
    for (int mi = 0; mi < 2; mi++) {
        const int rA = row0 + warp_m * 32 + mi * 16 + g;
        const int rB = rA + 8;
        #pragma unroll
        for (int u = 0; u < 4; u++) {
            const int col = col0 + warp_n * 32 + u * 8 + tq * 2;
            float ra, rb;
            if (rA < n_e) {
                float a = acc[mi][u][0], b = acc[mi][u][1];
                a = a / (1.0f + __expf(-a));
                b = b / (1.0f + __expf(-b));
                uint32_t hi = pack_hi(a, b, ra, rb);
                uint32_t lo = pack_bf2(ra, rb);
                size_t idx = ((size_t)e * T_ + rA) * FF_ + col;
                *(uint32_t*)(g_h_hi + idx) = hi;
                *(uint32_t*)(g_h_lo + idx) = lo;
            }
            if (rB < n_e) {
                float a = acc[mi][u][2], b = acc[mi][u][3];
                a = a / (1.0f + __expf(-a));
                b = b / (1.0f + __expf(-b));
                uint32_t hi = pack_hi(a, b, ra, rb);
                uint32_t lo = pack_bf2(ra, rb);
                size_t idx = ((size_t)e * T_ + rB) * FF_ + col;
                *(uint32_t*)(g_h_hi + idx) = hi;
                *(uint32_t*)(g_h_lo + idx) = lo;
            }
        }
    }
}

// ---------------------------------------------------------------------------
// GEMM2: out[tok(s),n] += wt(s) * ( H[s,:] . W2[e,n,:] )
// ---------------------------------------------------------------------------
__global__ void __launch_bounds__(512, 1)
expert_gemm2_mma(const float* __restrict__ w2, float* __restrict__ out) {
    extern __shared__ char smem[];
    const int e = blockIdx.z;
    const int n_e = g_cnt[e];
    const int row0 = blockIdx.y * BM;
    if (row0 >= n_e) return;
    const int col0 = blockIdx.x * BN;
    const int tid = threadIdx.x, wid = tid >> 5, lane = tid & 31;

    int*   toks = (int*)smem;
    float* wts  = (float*)(smem + 512);
    if (tid < BM) {
        int r = row0 + tid;
        if (r < n_e) { toks[tid] = g_tok[e * T_ + r]; wts[tid] = g_wt[e * T_ + r]; }
        else         { toks[tid] = 0;                 wts[tid] = 0.0f; }
    }
    __syncthreads();
    const uint32_t sb = smem_u32(smem);

    // loader role: 4 threads per row, 16 elements each
    const int lr = tid >> 2, q = tid & 3;
    const size_t arow = (size_t)e * T_ + row0 + lr;
    const __nv_bfloat16* ahp = g_h_hi + arow * FF_ + q * 16;
    const __nv_bfloat16* alp = g_h_lo + arow * FF_ + q * 16;
    const float* bptr = w2 + (size_t)e * D_ * FF_ + (size_t)(col0 + lr) * FF_ + q * 16;
    const uint32_t offA = swz(lr, q * 2), offB = swz(lr, q * 2 + 1);

    // mma role
    const int warp_m = wid & 3, warp_n = wid >> 2;
    const int a_r = warp_m * 32 + (lane & 15);
    const int a_c = lane >> 4;
    const int b_r = warp_n * 32 + (lane & 7) + ((lane >> 4) & 1) * 8;
    const int b_c = (lane >> 3) & 1;

    float acc[2][4][4] = {};
    uint4 h0, h1, l0, l1;
    float4 fb[4];
    h0 = *(const uint4*)ahp;  h1 = *((const uint4*)ahp + 1);
    l0 = *(const uint4*)alp;  l1 = *((const uint4*)alp + 1);
    load16f(fb, bptr);

    const int S = FF_ / BK;
    #pragma unroll 1
    for (int s = 0; s < S; s++) {
        char* bufc = smem + SOFF_BUF + (s & 1) * STAGE;
        *(uint4*)(bufc + AH_OFF + offA) = h0;
        *(uint4*)(bufc + AH_OFF + offB) = h1;
        *(uint4*)(bufc + AL_OFF + offA) = l0;
        *(uint4*)(bufc + AL_OFF + offB) = l1;
        split16(bufc + BH_OFF, bufc + BL_OFF, offA, offB, fb);
        __syncthreads();
        if (s + 1 < S) {
            const int k1 = (s + 1) * BK;
            h0 = *(const uint4*)(ahp + k1);  h1 = *((const uint4*)(ahp + k1) + 1);
            l0 = *(const uint4*)(alp + k1);  l1 = *((const uint4*)(alp + k1) + 1);
            load16f(fb, bptr + k1);
        }
        mma_stage(sb + SOFF_BUF + (s & 1) * STAGE, a_r, a_c, b_r, b_c, acc);
    }

    // epilogue: weighted atomic scatter
    const int g = lane >> 2, tq = lane & 3;
    #pragma unroll
    for (int mi = 0; mi < 2; mi++) {
        const int rlA = warp_m * 32 + mi * 16 + g;
        const int rlB = rlA + 8;
        #pragma unroll
        for (int u = 0; u < 4; u++) {
            const int col = col0 + warp_n * 32 + u * 8 + tq * 2;
            if (row0 + rlA < n_e) {
                float w = wts[rlA];
                float* o = out + (size_t)toks[rlA] * D_ + col;
                atomicAdd(o,     w * acc[mi][u][0]);
                atomicAdd(o + 1, w * acc[mi][u][1]);
            }
            if (row0 + rlB < n_e) {
                float w = wts[rlB];
                float* o = out + (size_t)toks[rlB] * D_ + col;
                atomicAdd(o,     w * acc[mi][u][2]);
                atomicAdd(o + 1, w * acc[mi][u][3]);
            }
        }
    }
}

// ---------------------------------------------------------------------------
extern "C" void kernel_launch(void* const* d_in, const int* in_sizes, int n_in,
                              void* d_out, int out_size) {
    const float* x  = (const float*)d_in[0];
    const float* rw = (const float*)d_in[1];
    const float* w1 = (const float*)d_in[2];
    const float* w2 = (const float*)d_in[3];
    float* out = (float*)d_out;

    cudaFuncSetAttribute(expert_gemm1_mma,
                         cudaFuncAttributeMaxDynamicSharedMemorySize, SMEM_TOTAL);
    cudaFuncSetAttribute(expert_gemm2_mma,
                         cudaFuncAttributeMaxDynamicSharedMemorySize, SMEM_TOTAL);

    zero_kernel<<<(out_size + 255) / 256, 256>>>(out, out_size);
    router_kernel<<<T_, 256>>>(x, rw, out, out_size);
    expert_gemm1_mma<<<dim3(FF_ / BN, T_ / BM, E_), 512, SMEM_TOTAL>>>(x, w1);
    expert_gemm2_mma<<<dim3(D_ / BN, T_ / BM, E_), 512, SMEM_TOTAL>>>(w2, out);
}

// round 7
// speedup vs baseline: 1.3278x; 1.3278x over previous
#include <cuda_runtime.h>
#include <cuda_fp16.h>
#include <math.h>
#include <stdint.h>

// Problem constants
#define B_   2
#define S_   1024
#define D_   1024
#define E_   8
#define KTOP 2
#define FF_  2048
#define T_   (B_ * S_)
#define OUT_MAIN (T_ * D_)
#define OUT_FULL (OUT_MAIN + T_*E_ + T_*KTOP + T_*KTOP)
#define NW   (E_ * FF_ * D_)     // 16,777,216 weights per matrix

// GEMM tiling: 128x128x64 stages, 512 threads / 16 warps (4x4), warp tile 32x32
#define BM 128
#define BN 128
#define BK 64
// smem stage: A_hi 16K | A_lo 16K | B 16K  (128 rows x 64 fp16 = 128B/row)
#define AH_OFF 0
#define AL_OFF 16384
#define BB_OFF 32768
#define STAGE  49152
#define SOFF_BUF 1024          // toks [0,512), wts [512,1024)
#define SMEM_TOTAL (SOFF_BUF + 2 * STAGE)   // 99328

// Device scratch
__device__ int   g_cnt[E_];
__device__ int   g_tok[E_ * T_];
__device__ float g_wt [E_ * T_];
__device__ __half g_w1h[(size_t)NW];
__device__ __half g_w2h[(size_t)NW];
__device__ __half g_xh[(size_t)T_ * D_];
__device__ __half g_xl[(size_t)T_ * D_];
__device__ __half g_h_hi[(size_t)E_ * T_ * FF_];
__device__ __half g_h_lo[(size_t)E_ * T_ * FF_];

// ---------------------------------------------------------------------------
__device__ __forceinline__ uint32_t smem_u32(const void* p) {
    uint32_t a;
    asm("{ .reg .u64 t; cvta.to.shared.u64 t, %1; cvt.u32.u64 %0, t; }"
        : "=r"(a) : "l"(p));
    return a;
}

// swizzled byte offset inside a [rows][64 fp16] tile (128B rows, 8 x 16B chunks)
__device__ __forceinline__ uint32_t swz(int r, int c) {
    return (uint32_t)(r * 128 + ((c ^ (r & 7)) << 4));
}

__device__ __forceinline__ void ldsm_x4(uint32_t addr, uint32_t r[4]) {
    asm volatile("ldmatrix.sync.aligned.m8n8.x4.shared.b16 {%0,%1,%2,%3}, [%4];"
                 : "=r"(r[0]), "=r"(r[1]), "=r"(r[2]), "=r"(r[3]) : "r"(addr));
}

__device__ __forceinline__ void mma_fp16(float c[4], const uint32_t a[4],
                                         uint32_t b0, uint32_t b1) {
    asm volatile("mma.sync.aligned.m16n8k16.row.col.f32.f16.f16.f32 "
                 "{%0,%1,%2,%3}, {%4,%5,%6,%7}, {%8,%9}, {%0,%1,%2,%3};"
                 : "+f"(c[0]), "+f"(c[1]), "+f"(c[2]), "+f"(c[3])
                 : "r"(a[0]), "r"(a[1]), "r"(a[2]), "r"(a[3]),
                   "r"(b0), "r"(b1));
}

__device__ __forceinline__ uint32_t packh_hi(float a, float b, float& ra, float& rb) {
    __half2 h = __floats2half2_rn(a, b);
    ra = a - __low2float(h);
    rb = b - __high2float(h);
    return *reinterpret_cast<uint32_t*>(&h);
}
__device__ __forceinline__ uint32_t packh(float a, float b) {
    __half2 h = __floats2half2_rn(a, b);
    return *reinterpret_cast<uint32_t*>(&h);
}

// ---------------------------------------------------------------------------
__global__ void zero_kernel(float* __restrict__ out, int n) {
    int i = blockIdx.x * blockDim.x + threadIdx.x;
    if (i < n) out[i] = 0.0f;
    if (blockIdx.x == 0 && threadIdx.x < E_) g_cnt[threadIdx.x] = 0;
}

// ---------------------------------------------------------------------------
// convert weights to fp16 (single), 4 elems/thread
__global__ void conv_w_kernel(const float* __restrict__ w1,
                              const float* __restrict__ w2) {
    size_t i = ((size_t)blockIdx.x * blockDim.x + threadIdx.x) * 4;
    const float* src;
    __half* dst;
    if (i < (size_t)NW) { src = w1 + i;        dst = g_w1h + i; }
    else                { src = w2 + (i - NW); dst = g_w2h + (i - NW); }
    float4 v = *(const float4*)src;
    uint32_t p0 = packh(v.x, v.y);
    uint32_t p1 = packh(v.z, v.w);
    *(uint32_t*)dst       = p0;
    *(uint32_t*)(dst + 2) = p1;
}

// convert x to split fp16 hi/lo
__global__ void conv_x_kernel(const float* __restrict__ x) {
    int i = (blockIdx.x * blockDim.x + threadIdx.x) * 4;
    float4 v = *(const float4*)(x + i);
    float r0, r1, r2, r3;
    uint32_t h0 = packh_hi(v.x, v.y, r0, r1);
    uint32_t h1 = packh_hi(v.z, v.w, r2, r3);
    *(uint32_t*)(g_xh + i)     = h0;
    *(uint32_t*)(g_xh + i + 2) = h1;
    *(uint32_t*)(g_xl + i)     = packh(r0, r1);
    *(uint32_t*)(g_xl + i + 2) = packh(r2, r3);
}

// ---------------------------------------------------------------------------
__global__ void router_kernel(const float* __restrict__ x,
                              const float* __restrict__ rw,
                              float* __restrict__ out, int out_size) {
    const int t = blockIdx.x;
    __shared__ float xs[D_];
    __shared__ float logits[E_];

    for (int i = threadIdx.x; i < D_; i += blockDim.x)
        xs[i] = x[(size_t)t * D_ + i];
    __syncthreads();

    const int w = threadIdx.x >> 5;
    const int lane = threadIdx.x & 31;
    float s = 0.0f;
    const float* rwe = rw + (size_t)w * D_;
    for (int k = lane; k < D_; k += 32) s += xs[k] * rwe[k];
    #pragma unroll
    for (int o = 16; o; o >>= 1) s += __shfl_xor_sync(0xffffffffu, s, o);
    if (lane == 0) logits[w] = s;
    __syncthreads();

    if (threadIdx.x == 0) {
        float mx = logits[0];
        #pragma unroll
        for (int e = 1; e < E_; e++) mx = fmaxf(mx, logits[e]);
        float p[E_]; float sum = 0.0f;
        #pragma unroll
        for (int e = 0; e < E_; e++) { p[e] = expf(logits[e] - mx); sum += p[e]; }
        float inv = 1.0f / sum;
        #pragma unroll
        for (int e = 0; e < E_; e++) p[e] *= inv;

        int i0 = 0;
        #pragma unroll
        for (int e = 1; e < E_; e++) if (p[e] > p[i0]) i0 = e;
        int i1 = (i0 == 0) ? 1 : 0;
        #pragma unroll
        for (int e = 0; e < E_; e++) if (e != i0 && p[e] > p[i1]) i1 = e;

        float w0 = p[i0], w1 = p[i1];
        float rinv = 1.0f / (w0 + w1);
        w0 *= rinv; w1 *= rinv;

        int s0 = atomicAdd(&g_cnt[i0], 1);
        g_tok[i0 * T_ + s0] = t; g_wt[i0 * T_ + s0] = w0;
        int s1 = atomicAdd(&g_cnt[i1], 1);
        g_tok[i1 * T_ + s1] = t; g_wt[i1 * T_ + s1] = w1;

        if (out_size >= OUT_FULL) {
            float* probs = out + OUT_MAIN;
            float* idxs  = out + OUT_MAIN + T_ * E_;
            float* wts   = out + OUT_MAIN + T_ * E_ + T_ * KTOP;
            #pragma unroll
            for (int e = 0; e < E_; e++) probs[t * E_ + e] = p[e];
            idxs[t * KTOP + 0] = (float)i0;
            idxs[t * KTOP + 1] = (float)i1;
            wts [t * KTOP + 0] = w0;
            wts [t * KTOP + 1] = w1;
        }
    }
}

// ---------------------------------------------------------------------------
// one pipeline stage's MMA phase: warp tile 32x32, 2 passes (hi*B, lo*B)
// ---------------------------------------------------------------------------
__device__ __forceinline__ void mma_stage(uint32_t base, int a_r, int a_c,
                                          int b_r, int b_c,
                                          float acc[2][4][4]) {
    #pragma unroll
    for (int ks = 0; ks < 4; ks++) {
        uint32_t ah[2][4], al[2][4], bh[2][4];
        #pragma unroll
        for (int mi = 0; mi < 2; mi++) {
            uint32_t off = swz(a_r + mi * 16, ks * 2 + a_c);
            ldsm_x4(base + AH_OFF + off, ah[mi]);
            ldsm_x4(base + AL_OFF + off, al[mi]);
        }
        #pragma unroll
        for (int nj = 0; nj < 2; nj++) {
            uint32_t off = swz(b_r + nj * 16, ks * 2 + b_c);
            ldsm_x4(base + BB_OFF + off, bh[nj]);
        }
        // pass 1: A_hi * B
        #pragma unroll
        for (int mi = 0; mi < 2; mi++)
            #pragma unroll
            for (int nj = 0; nj < 2; nj++)
                #pragma unroll
                for (int h = 0; h < 2; h++)
                    mma_fp16(acc[mi][nj*2+h], ah[mi], bh[nj][h*2], bh[nj][h*2+1]);
        // pass 2: A_lo * B
        #pragma unroll
        for (int mi = 0; mi < 2; mi++)
            #pragma unroll
            for (int nj = 0; nj < 2; nj++)
                #pragma unroll
                for (int h = 0; h < 2; h++)
                    mma_fp16(acc[mi][nj*2+h], al[mi], bh[nj][h*2], bh[nj][h*2+1]);
    }
}

// ---------------------------------------------------------------------------
// GEMM1: H[s,n] = silu( X[tok(s),:] . W1[e,n,:] ), H stored split fp16 hi/lo
// ---------------------------------------------------------------------------
__global__ void __launch_bounds__(512, 1)
expert_gemm1_mma(const float* __restrict__ xunused, const float* __restrict__ w1u) {
    extern __shared__ char smem[];
    const int e = blockIdx.z;
    const int n_e = g_cnt[e];
    const int row0 = blockIdx.y * BM;
    if (row0 >= n_e) return;
    const int col0 = blockIdx.x * BN;
    const int tid = threadIdx.x, wid = tid >> 5, lane = tid & 31;

    int* toks = (int*)smem;
    if (tid < BM) {
        int r = row0 + tid;
        toks[tid] = (r < n_e) ? g_tok[e * T_ + r] : -1;
    }
    __syncthreads();
    const uint32_t sb = smem_u32(smem);

    // loader role: 4 threads per row, 16 fp16 each per tile
    const int lr = tid >> 2, q = tid & 3;
    const int tok = toks[lr];
    const __half* ahp = g_xh + (size_t)(tok < 0 ? 0 : tok) * D_ + q * 16;
    const __half* alp = g_xl + (size_t)(tok < 0 ? 0 : tok) * D_ + q * 16;
    const __half* bp  = g_w1h + (size_t)e * FF_ * D_ + (size_t)(col0 + lr) * D_ + q * 16;
    const bool valid = (tok >= 0);
    const uint32_t offA = swz(lr, q * 2), offB = swz(lr, q * 2 + 1);

    // mma role: 4x4 warp grid, warp tile 32x32
    const int warp_m = wid & 3, warp_n = wid >> 2;
    const int a_r = warp_m * 32 + (lane & 15);
    const int a_c = lane >> 4;
    const int b_r = warp_n * 32 + (lane & 7) + ((lane >> 4) & 1) * 8;
    const int b_c = (lane >> 3) & 1;

    float acc[2][4][4] = {};
    const uint4 Z = make_uint4(0, 0, 0, 0);
    uint4 va0, va1, vl0, vl1, vb0, vb1;
    va0 = valid ? *(const uint4*)ahp : Z;
    va1 = valid ? *((const uint4*)ahp + 1) : Z;
    vl0 = valid ? *(const uint4*)alp : Z;
    vl1 = valid ? *((const uint4*)alp + 1) : Z;
    vb0 = *(const uint4*)bp;
    vb1 = *((const uint4*)bp + 1);

    const int S = D_ / BK;
    #pragma unroll 1
    for (int s = 0; s < S; s++) {
        char* bufc = smem + SOFF_BUF + (s & 1) * STAGE;
        *(uint4*)(bufc + AH_OFF + offA) = va0;
        *(uint4*)(bufc + AH_OFF + offB) = va1;
        *(uint4*)(bufc + AL_OFF + offA) = vl0;
        *(uint4*)(bufc + AL_OFF + offB) = vl1;
        *(uint4*)(bufc + BB_OFF + offA) = vb0;
        *(uint4*)(bufc + BB_OFF + offB) = vb1;
        __syncthreads();
        if (s + 1 < S) {
            const int k1 = (s + 1) * BK;
            va0 = valid ? *(const uint4*)(ahp + k1) : Z;
            va1 = valid ? *((const uint4*)(ahp + k1) + 1) : Z;
            vl0 = valid ? *(const uint4*)(alp + k1) : Z;
            vl1 = valid ? *((const uint4*)(alp + k1) + 1) : Z;
            vb0 = *(const uint4*)(bp + k1);
            vb1 = *((const uint4*)(bp + k1) + 1);
        }
        mma_stage(sb + SOFF_BUF + (s & 1) * STAGE, a_r, a_c, b_r, b_c, acc);
    }

    // epilogue: silu -> split fp16 -> g_h
    const int g = lane >> 2, tq = lane & 3;
    #pragma unroll
    for (int mi = 0; mi < 2; mi++) {
        const int rA = row0 + warp_m * 32 + mi * 16 + g;
        const int rB = rA + 8;
        #pragma unroll
        for (int u = 0; u < 4; u++) {
            const int col = col0 + warp_n * 32 + u * 8 + tq * 2;
            float ra, rb;
            if (rA < n_e) {
                float a = acc[mi][u][0], b = acc[mi][u][1];
                a = a / (1.0f + __expf(-a));
                b = b / (1.0f + __expf(-b));
                uint32_t hi = packh_hi(a, b, ra, rb);
                uint32_t lo = packh(ra, rb);
                size_t idx = ((size_t)e * T_ + rA) * FF_ + col;
                *(uint32_t*)(g_h_hi + idx) = hi;
                *(uint32_t*)(g_h_lo + idx) = lo;
            }
            if (rB < n_e) {
                float a = acc[mi][u][2], b = acc[mi][u][3];
                a = a / (1.0f + __expf(-a));
                b = b / (1.0f + __expf(-b));
                uint32_t hi = packh_hi(a, b, ra, rb);
                uint32_t lo = packh(ra, rb);
                size_t idx = ((size_t)e * T_ + rB) * FF_ + col;
                *(uint32_t*)(g_h_hi + idx) = hi;
                *(uint32_t*)(g_h_lo + idx) = lo;
            }
        }
    }
}

// ---------------------------------------------------------------------------
// GEMM2: out[tok(s),n] += wt(s) * ( H[s,:] . W2[e,n,:] )
// ---------------------------------------------------------------------------
__global__ void __launch_bounds__(512, 1)
expert_gemm2_mma(const float* __restrict__ w2u, float* __restrict__ out) {
    extern __shared__ char smem[];
    const int e = blockIdx.z;
    const int n_e = g_cnt[e];
    const int row0 = blockIdx.y * BM;
    if (row0 >= n_e) return;
    const int col0 = blockIdx.x * BN;
    const int tid = threadIdx.x, wid = tid >> 5, lane = tid & 31;

    int*   toks = (int*)smem;
    float* wts  = (float*)(smem + 512);
    if (tid < BM) {
        int r = row0 + tid;
        if (r < n_e) { toks[tid] = g_tok[e * T_ + r]; wts[tid] = g_wt[e * T_ + r]; }
        else         { toks[tid] = 0;                 wts[tid] = 0.0f; }
    }
    __syncthreads();
    const uint32_t sb = smem_u32(smem);

    // loader role
    const int lr = tid >> 2, q = tid & 3;
    const size_t arow = (size_t)e * T_ + row0 + lr;
    const __half* ahp = g_h_hi + arow * FF_ + q * 16;
    const __half* alp = g_h_lo + arow * FF_ + q * 16;
    const __half* bp  = g_w2h + (size_t)e * D_ * FF_ + (size_t)(col0 + lr) * FF_ + q * 16;
    const uint32_t offA = swz(lr, q * 2), offB = swz(lr, q * 2 + 1);

    // mma role
    const int warp_m = wid & 3, warp_n = wid >> 2;
    const int a_r = warp_m * 32 + (lane & 15);
    const int a_c = lane >> 4;
    const int b_r = warp_n * 32 + (lane & 7) + ((lane >> 4) & 1) * 8;
    const int b_c = (lane >> 3) & 1;

    float acc[2][4][4] = {};
    uint4 va0, va1, vl0, vl1, vb0, vb1;
    va0 = *(const uint4*)ahp;       va1 = *((const uint4*)ahp + 1);
    vl0 = *(const uint4*)alp;       vl1 = *((const uint4*)alp + 1);
    vb0 = *(const uint4*)bp;        vb1 = *((const uint4*)bp + 1);

    const int S = FF_ / BK;
    #pragma unroll 1
    for (int s = 0; s < S; s++) {
        char* bufc = smem + SOFF_BUF + (s & 1) * STAGE;
        *(uint4*)(bufc + AH_OFF + offA) = va0;
        *(uint4*)(bufc + AH_OFF + offB) = va1;
        *(uint4*)(bufc + AL_OFF + offA) = vl0;
        *(uint4*)(bufc + AL_OFF + offB) = vl1;
        *(uint4*)(bufc + BB_OFF + offA) = vb0;
        *(uint4*)(bufc + BB_OFF + offB) = vb1;
        __syncthreads();
        if (s + 1 < S) {
            const int k1 = (s + 1) * BK;
            va0 = *(const uint4*)(ahp + k1);  va1 = *((const uint4*)(ahp + k1) + 1);
            vl0 = *(const uint4*)(alp + k1);  vl1 = *((const uint4*)(alp + k1) + 1);
            vb0 = *(const uint4*)(bp + k1);   vb1 = *((const uint4*)(bp + k1) + 1);
        }
        mma_stage(sb + SOFF_BUF + (s & 1) * STAGE, a_r, a_c, b_r, b_c, acc);
    }

    // epilogue: weighted atomic scatter
    const int g = lane >> 2, tq = lane & 3;
    #pragma unroll
    for (int mi = 0; mi < 2; mi++) {
        const int rlA = warp_m * 32 + mi * 16 + g;
        const int rlB = rlA + 8;
        #pragma unroll
        for (int u = 0; u < 4; u++) {
            const int col = col0 + warp_n * 32 + u * 8 + tq * 2;
            if (row0 + rlA < n_e) {
                float w = wts[rlA];
                float* o = out + (size_t)toks[rlA] * D_ + col;
                atomicAdd(o,     w * acc[mi][u][0]);
                atomicAdd(o + 1, w * acc[mi][u][1]);
            }
            if (row0 + rlB < n_e) {
                float w = wts[rlB];
                float* o = out + (size_t)toks[rlB] * D_ + col;
                atomicAdd(o,     w * acc[mi][u][2]);
                atomicAdd(o + 1, w * acc[mi][u][3]);
            }
        }
    }
}

// ---------------------------------------------------------------------------
extern "C" void kernel_launch(void* const* d_in, const int* in_sizes, int n_in,
                              void* d_out, int out_size) {
    const float* x  = (const float*)d_in[0];
    const float* rw = (const float*)d_in[1];
    const float* w1 = (const float*)d_in[2];
    const float* w2 = (const float*)d_in[3];
    float* out = (float*)d_out;

    cudaFuncSetAttribute(expert_gemm1_mma,
                         cudaFuncAttributeMaxDynamicSharedMemorySize, SMEM_TOTAL);
    cudaFuncSetAttribute(expert_gemm2_mma,
                         cudaFuncAttributeMaxDynamicSharedMemorySize, SMEM_TOTAL);

    zero_kernel<<<(out_size + 255) / 256, 256>>>(out, out_size);
    conv_w_kernel<<<(2 * NW / 4) / 256, 256>>>(w1, w2);
    conv_x_kernel<<<(T_ * D_ / 4) / 256, 256>>>(x);
    router_kernel<<<T_, 256>>>(x, rw, out, out_size);
    expert_gemm1_mma<<<dim3(FF_ / BN, T_ / BM, E_), 512, SMEM_TOTAL>>>(x, w1);
    expert_gemm2_mma<<<dim3(D_ / BN, T_ / BM, E_), 512, SMEM_TOTAL>>>(w2, out);
}

// round 8
// speedup vs baseline: 1.7520x; 1.3194x over previous
#include <cuda_runtime.h>
#include <cuda_fp16.h>
#include <math.h>
#include <stdint.h>

// Problem constants
#define B_   2
#define S_   1024
#define D_   1024
#define E_   8
#define KTOP 2
#define FF_  2048
#define T_   (B_ * S_)
#define OUT_MAIN (T_ * D_)
#define OUT_FULL (OUT_MAIN + T_*E_ + T_*KTOP + T_*KTOP)
#define NW   (E_ * FF_ * D_)

// GEMM tiling: 128x128x64 stages, 512 threads / 16 warps (4x4), warp tile 32x32
#define BM 128
#define BN 128
#define BK 64
// smem stage: A 16K | B 16K  (128 rows x 64 fp16 = 128B/row)
#define AA_OFF 0
#define BB_OFF 16384
#define STAGE  32768
#define SOFF_BUF 1024          // toks [0,512), wts [512,1024)
#define SMEM_TOTAL (SOFF_BUF + 2 * STAGE)   // 66560

// Device scratch
__device__ int   g_cnt[E_];
__device__ int   g_tok[E_ * T_];
__device__ float g_wt [E_ * T_];
__device__ __half g_w1h[(size_t)NW];
__device__ __half g_w2h[(size_t)NW];
__device__ __half g_xh[(size_t)T_ * D_];
__device__ __half g_hh[(size_t)E_ * T_ * FF_];

// ---------------------------------------------------------------------------
__device__ __forceinline__ uint32_t smem_u32(const void* p) {
    uint32_t a;
    asm("{ .reg .u64 t; cvta.to.shared.u64 t, %1; cvt.u32.u64 %0, t; }"
        : "=r"(a) : "l"(p));
    return a;
}

// swizzled byte offset inside a [rows][64 fp16] tile (128B rows, 8 x 16B chunks)
__device__ __forceinline__ uint32_t swz(int r, int c) {
    return (uint32_t)(r * 128 + ((c ^ (r & 7)) << 4));
}

__device__ __forceinline__ void ldsm_x4(uint32_t addr, uint32_t r[4]) {
    asm volatile("ldmatrix.sync.aligned.m8n8.x4.shared.b16 {%0,%1,%2,%3}, [%4];"
                 : "=r"(r[0]), "=r"(r[1]), "=r"(r[2]), "=r"(r[3]) : "r"(addr));
}

__device__ __forceinline__ void mma_fp16(float c[4], const uint32_t a[4],
                                         uint32_t b0, uint32_t b1) {
    asm volatile("mma.sync.aligned.m16n8k16.row.col.f32.f16.f16.f32 "
                 "{%0,%1,%2,%3}, {%4,%5,%6,%7}, {%8,%9}, {%0,%1,%2,%3};"
                 : "+f"(c[0]), "+f"(c[1]), "+f"(c[2]), "+f"(c[3])
                 : "r"(a[0]), "r"(a[1]), "r"(a[2]), "r"(a[3]),
                   "r"(b0), "r"(b1));
}

__device__ __forceinline__ uint32_t packh(float a, float b) {
    __half2 h = __floats2half2_rn(a, b);
    return *reinterpret_cast<uint32_t*>(&h);
}

// ---------------------------------------------------------------------------
__global__ void zero_kernel(float* __restrict__ out, int n) {
    int i = blockIdx.x * blockDim.x + threadIdx.x;
    if (i < n) out[i] = 0.0f;
    if (blockIdx.x == 0 && threadIdx.x < E_) g_cnt[threadIdx.x] = 0;
}

// ---------------------------------------------------------------------------
// convert weights to fp16, 4 elems/thread
__global__ void conv_w_kernel(const float* __restrict__ w1,
                              const float* __restrict__ w2) {
    size_t i = ((size_t)blockIdx.x * blockDim.x + threadIdx.x) * 4;
    const float* src;
    __half* dst;
    if (i < (size_t)NW) { src = w1 + i;        dst = g_w1h + i; }
    else                { src = w2 + (i - NW); dst = g_w2h + (i - NW); }
    float4 v = *(const float4*)src;
    *(uint32_t*)dst       = packh(v.x, v.y);
    *(uint32_t*)(dst + 2) = packh(v.z, v.w);
}

// convert x to fp16
__global__ void conv_x_kernel(const float* __restrict__ x) {
    int i = (blockIdx.x * blockDim.x + threadIdx.x) * 4;
    float4 v = *(const float4*)(x + i);
    *(uint32_t*)(g_xh + i)     = packh(v.x, v.y);
    *(uint32_t*)(g_xh + i + 2) = packh(v.z, v.w);
}

// ---------------------------------------------------------------------------
__global__ void router_kernel(const float* __restrict__ x,
                              const float* __restrict__ rw,
                              float* __restrict__ out, int out_size) {
    const int t = blockIdx.x;
    __shared__ float xs[D_];
    __shared__ float logits[E_];

    for (int i = threadIdx.x; i < D_; i += blockDim.x)
        xs[i] = x[(size_t)t * D_ + i];
    __syncthreads();

    const int w = threadIdx.x >> 5;
    const int lane = threadIdx.x & 31;
    float s = 0.0f;
    const float* rwe = rw + (size_t)w * D_;
    for (int k = lane; k < D_; k += 32) s += xs[k] * rwe[k];
    #pragma unroll
    for (int o = 16; o; o >>= 1) s += __shfl_xor_sync(0xffffffffu, s, o);
    if (lane == 0) logits[w] = s;
    __syncthreads();

    if (threadIdx.x == 0) {
        float mx = logits[0];
        #pragma unroll
        for (int e = 1; e < E_; e++) mx = fmaxf(mx, logits[e]);
        float p[E_]; float sum = 0.0f;
        #pragma unroll
        for (int e = 0; e < E_; e++) { p[e] = expf(logits[e] - mx); sum += p[e]; }
        float inv = 1.0f / sum;
        #pragma unroll
        for (int e = 0; e < E_; e++) p[e] *= inv;

        int i0 = 0;
        #pragma unroll
        for (int e = 1; e < E_; e++) if (p[e] > p[i0]) i0 = e;
        int i1 = (i0 == 0) ? 1 : 0;
        #pragma unroll
        for (int e = 0; e < E_; e++) if (e != i0 && p[e] > p[i1]) i1 = e;

        float w0 = p[i0], w1 = p[i1];
        float rinv = 1.0f / (w0 + w1);
        w0 *= rinv; w1 *= rinv;

        int s0 = atomicAdd(&g_cnt[i0], 1);
        g_tok[i0 * T_ + s0] = t; g_wt[i0 * T_ + s0] = w0;
        int s1 = atomicAdd(&g_cnt[i1], 1);
        g_tok[i1 * T_ + s1] = t; g_wt[i1 * T_ + s1] = w1;

        if (out_size >= OUT_FULL) {
            float* probs = out + OUT_MAIN;
            float* idxs  = out + OUT_MAIN + T_ * E_;
            float* wts   = out + OUT_MAIN + T_ * E_ + T_ * KTOP;
            #pragma unroll
            for (int e = 0; e < E_; e++) probs[t * E_ + e] = p[e];
            idxs[t * KTOP + 0] = (float)i0;
            idxs[t * KTOP + 1] = (float)i1;
            wts [t * KTOP + 0] = w0;
            wts [t * KTOP + 1] = w1;
        }
    }
}

// ---------------------------------------------------------------------------
// one pipeline stage's MMA phase: warp tile 32x32, single fp16 pass
// ---------------------------------------------------------------------------
__device__ __forceinline__ void mma_stage(uint32_t base, int a_r, int a_c,
                                          int b_r, int b_c,
                                          float acc[2][4][4]) {
    #pragma unroll
    for (int ks = 0; ks < 4; ks++) {
        uint32_t ah[2][4], bh[2][4];
        #pragma unroll
        for (int mi = 0; mi < 2; mi++)
            ldsm_x4(base + AA_OFF + swz(a_r + mi * 16, ks * 2 + a_c), ah[mi]);
        #pragma unroll
        for (int nj = 0; nj < 2; nj++)
            ldsm_x4(base + BB_OFF + swz(b_r + nj * 16, ks * 2 + b_c), bh[nj]);
        #pragma unroll
        for (int mi = 0; mi < 2; mi++)
            #pragma unroll
            for (int nj = 0; nj < 2; nj++)
                #pragma unroll
                for (int h = 0; h < 2; h++)
                    mma_fp16(acc[mi][nj*2+h], ah[mi], bh[nj][h*2], bh[nj][h*2+1]);
    }
}

// ---------------------------------------------------------------------------
// GEMM1: H[s,n] = silu( X[tok(s),:] . W1[e,n,:] ), H stored fp16
// ---------------------------------------------------------------------------
__global__ void __launch_bounds__(512)
expert_gemm1_mma() {
    extern __shared__ char smem[];
    const int e = blockIdx.z;
    const int n_e = g_cnt[e];
    const int row0 = blockIdx.y * BM;
    if (row0 >= n_e) return;
    const int col0 = blockIdx.x * BN;
    const int tid = threadIdx.x, wid = tid >> 5, lane = tid & 31;

    int* toks = (int*)smem;
    if (tid < BM) {
        int r = row0 + tid;
        toks[tid] = (r < n_e) ? g_tok[e * T_ + r] : -1;
    }
    __syncthreads();
    const uint32_t sb = smem_u32(smem);

    // loader role: 4 threads per row, 16 fp16 each
    const int lr = tid >> 2, q = tid & 3;
    const int tok = toks[lr];
    const __half* ap = g_xh + (size_t)(tok < 0 ? 0 : tok) * D_ + q * 16;
    const __half* bp = g_w1h + (size_t)e * FF_ * D_ + (size_t)(col0 + lr) * D_ + q * 16;
    const bool valid = (tok >= 0);
    const uint32_t offA = swz(lr, q * 2), offB = swz(lr, q * 2 + 1);

    // mma role: 4x4 warp grid, warp tile 32x32
    const int warp_m = wid & 3, warp_n = wid >> 2;
    const int a_r = warp_m * 32 + (lane & 15);
    const int a_c = lane >> 4;
    const int b_r = warp_n * 32 + (lane & 7) + ((lane >> 4) & 1) * 8;
    const int b_c = (lane >> 3) & 1;

    float acc[2][4][4] = {};
    const uint4 Z = make_uint4(0, 0, 0, 0);
    uint4 va0, va1, vb0, vb1;
    va0 = valid ? *(const uint4*)ap : Z;
    va1 = valid ? *((const uint4*)ap + 1) : Z;
    vb0 = *(const uint4*)bp;
    vb1 = *((const uint4*)bp + 1);

    const int S = D_ / BK;
    #pragma unroll 1
    for (int s = 0; s < S; s++) {
        char* bufc = smem + SOFF_BUF + (s & 1) * STAGE;
        *(uint4*)(bufc + AA_OFF + offA) = va0;
        *(uint4*)(bufc + AA_OFF + offB) = va1;
        *(uint4*)(bufc + BB_OFF + offA) = vb0;
        *(uint4*)(bufc + BB_OFF + offB) = vb1;
        __syncthreads();
        if (s + 1 < S) {
            const int k1 = (s + 1) * BK;
            va0 = valid ? *(const uint4*)(ap + k1) : Z;
            va1 = valid ? *((const uint4*)(ap + k1) + 1) : Z;
            vb0 = *(const uint4*)(bp + k1);
            vb1 = *((const uint4*)(bp + k1) + 1);
        }
        mma_stage(sb + SOFF_BUF + (s & 1) * STAGE, a_r, a_c, b_r, b_c, acc);
    }

    // epilogue: silu -> fp16 -> g_hh
    const int g = lane >> 2, tq = lane & 3;
    #pragma unroll
    for (int mi = 0; mi < 2; mi++) {
        const int rA = row0 + warp_m * 32 + mi * 16 + g;
        const int rB = rA + 8;
        #pragma unroll
        for (int u = 0; u < 4; u++) {
            const int col = col0 + warp_n * 32 + u * 8 + tq * 2;
            if (rA < n_e) {
                float a = acc[mi][u][0], b = acc[mi][u][1];
                a = a / (1.0f + __expf(-a));
                b = b / (1.0f + __expf(-b));
                *(uint32_t*)(g_hh + ((size_t)e * T_ + rA) * FF_ + col) = packh(a, b);
            }
            if (rB < n_e) {
                float a = acc[mi][u][2], b = acc[mi][u][3];
                a = a / (1.0f + __expf(-a));
                b = b / (1.0f + __expf(-b));
                *(uint32_t*)(g_hh + ((size_t)e * T_ + rB) * FF_ + col) = packh(a, b);
            }
        }
    }
}

// ---------------------------------------------------------------------------
// GEMM2: out[tok(s),n] += wt(s) * ( H[s,:] . W2[e,n,:] )
// ---------------------------------------------------------------------------
__global__ void __launch_bounds__(512)
expert_gemm2_mma(float* __restrict__ out) {
    extern __shared__ char smem[];
    const int e = blockIdx.z;
    const int n_e = g_cnt[e];
    const int row0 = blockIdx.y * BM;
    if (row0 >= n_e) return;
    const int col0 = blockIdx.x * BN;
    const int tid = threadIdx.x, wid = tid >> 5, lane = tid & 31;

    int*   toks = (int*)smem;
    float* wts  = (float*)(smem + 512);
    if (tid < BM) {
        int r = row0 + tid;
        if (r < n_e) { toks[tid] = g_tok[e * T_ + r]; wts[tid] = g_wt[e * T_ + r]; }
        else         { toks[tid] = 0;                 wts[tid] = 0.0f; }
    }
    __syncthreads();
    const uint32_t sb = smem_u32(smem);

    // loader role
    const int lr = tid >> 2, q = tid & 3;
    const __half* ap = g_hh + ((size_t)e * T_ + row0 + lr) * FF_ + q * 16;
    const __half* bp = g_w2h + (size_t)e * D_ * FF_ + (size_t)(col0 + lr) * FF_ + q * 16;
    const uint32_t offA = swz(lr, q * 2), offB = swz(lr, q * 2 + 1);

    // mma role
    const int warp_m = wid & 3, warp_n = wid >> 2;
    const int a_r = warp_m * 32 + (lane & 15);
    const int a_c = lane >> 4;
    const int b_r = warp_n * 32 + (lane & 7) + ((lane >> 4) & 1) * 8;
    const int b_c = (lane >> 3) & 1;

    float acc[2][4][4] = {};
    uint4 va0, va1, vb0, vb1;
    va0 = *(const uint4*)ap;  va1 = *((const uint4*)ap + 1);
    vb0 = *(const uint4*)bp;  vb1 = *((const uint4*)bp + 1);

    const int S = FF_ / BK;
    #pragma unroll 1
    for (int s = 0; s < S; s++) {
        char* bufc = smem + SOFF_BUF + (s & 1) * STAGE;
        *(uint4*)(bufc + AA_OFF + offA) = va0;
        *(uint4*)(bufc + AA_OFF + offB) = va1;
        *(uint4*)(bufc + BB_OFF + offA) = vb0;
        *(uint4*)(bufc + BB_OFF + offB) = vb1;
        __syncthreads();
        if (s + 1 < S) {
            const int k1 = (s + 1) * BK;
            va0 = *(const uint4*)(ap + k1);  va1 = *((const uint4*)(ap + k1) + 1);
            vb0 = *(const uint4*)(bp + k1);  vb1 = *((const uint4*)(bp + k1) + 1);
        }
        mma_stage(sb + SOFF_BUF + (s & 1) * STAGE, a_r, a_c, b_r, b_c, acc);
    }

    // epilogue: weighted atomic scatter
    const int g = lane >> 2, tq = lane & 3;
    #pragma unroll
    for (int mi = 0; mi < 2; mi++) {
        const int rlA = warp_m * 32 + mi * 16 + g;
        const int rlB = rlA + 8;
        #pragma unroll
        for (int u = 0; u < 4; u++) {
            const int col = col0 + warp_n * 32 + u * 8 + tq * 2;
            if (row0 + rlA < n_e) {
                float w = wts[rlA];
                float* o = out + (size_t)toks[rlA] * D_ + col;
                atomicAdd(o,     w * acc[mi][u][0]);
                atomicAdd(o + 1, w * acc[mi][u][1]);
            }
            if (row0 + rlB < n_e) {
                float w = wts[rlB];
                float* o = out + (size_t)toks[rlB] * D_ + col;
                atomicAdd(o,     w * acc[mi][u][2]);
                atomicAdd(o + 1, w * acc[mi][u][3]);
            }
        }
    }
}

// ---------------------------------------------------------------------------
extern "C" void kernel_launch(void* const* d_in, const int* in_sizes, int n_in,
                              void* d_out, int out_size) {
    const float* x  = (const float*)d_in[0];
    const float* rw = (const float*)d_in[1];
    const float* w1 = (const float*)d_in[2];
    const float* w2 = (const float*)d_in[3];
    float* out = (float*)d_out;

    cudaFuncSetAttribute(expert_gemm1_mma,
                         cudaFuncAttributeMaxDynamicSharedMemorySize, SMEM_TOTAL);
    cudaFuncSetAttribute(expert_gemm2_mma,
                         cudaFuncAttributeMaxDynamicSharedMemorySize, SMEM_TOTAL);

    zero_kernel<<<(out_size + 255) / 256, 256>>>(out, out_size);
    conv_w_kernel<<<(2 * NW / 4) / 256, 256>>>(w1, w2);
    conv_x_kernel<<<(T_ * D_ / 4) / 256, 256>>>(x);
    router_kernel<<<T_, 256>>>(x, rw, out, out_size);
    expert_gemm1_mma<<<dim3(FF_ / BN, T_ / BM, E_), 512, SMEM_TOTAL>>>();
    expert_gemm2_mma<<<dim3(D_ / BN, T_ / BM, E_), 512, SMEM_TOTAL>>>(out);
}

// round 9
// speedup vs baseline: 2.2253x; 1.2702x over previous
#include <cuda_runtime.h>
#include <cuda_fp16.h>
#include <math.h>
#include <stdint.h>

// Problem constants
#define B_   2
#define S_   1024
#define D_   1024
#define E_   8
#define KTOP 2
#define FF_  2048
#define T_   (B_ * S_)
#define OUT_MAIN (T_ * D_)
#define OUT_FULL (OUT_MAIN + T_*E_ + T_*KTOP + T_*KTOP)
#define NW   (E_ * FF_ * D_)

// GEMM tiling: 128x256x64 stages, 512 threads / 16 warps (4x4), warp tile 32x64
#define BM 128
#define BN 256
#define BK 64
// smem stage: A 16K (128x64 fp16) | B 32K (256x64 fp16)
#define AA_OFF 0
#define BB_OFF 16384
#define STAGE  49152
#define NSTAGE 3
#define SOFF_BUF 1024          // toks [0,512), wts [512,1024)
#define SMEM_TOTAL (SOFF_BUF + NSTAGE * STAGE)   // 148480

// Device scratch
__device__ int   g_cnt[E_];
__device__ int   g_tok[E_ * T_];
__device__ float g_wt [E_ * T_];
__device__ __half g_w1h[(size_t)NW];
__device__ __half g_w2h[(size_t)NW];
__device__ __half g_xh[(size_t)T_ * D_];
__device__ __half g_hh[(size_t)E_ * T_ * FF_];

// ---------------------------------------------------------------------------
__device__ __forceinline__ uint32_t smem_u32(const void* p) {
    uint32_t a;
    asm("{ .reg .u64 t; cvta.to.shared.u64 t, %1; cvt.u32.u64 %0, t; }"
        : "=r"(a) : "l"(p));
    return a;
}

// swizzled byte offset inside a [rows][64 fp16] tile (128B rows, 8 x 16B chunks)
__device__ __forceinline__ uint32_t swz(int r, int c) {
    return (uint32_t)(r * 128 + ((c ^ (r & 7)) << 4));
}

__device__ __forceinline__ void ldsm_x4(uint32_t addr, uint32_t r[4]) {
    asm volatile("ldmatrix.sync.aligned.m8n8.x4.shared.b16 {%0,%1,%2,%3}, [%4];"
                 : "=r"(r[0]), "=r"(r[1]), "=r"(r[2]), "=r"(r[3]) : "r"(addr));
}

__device__ __forceinline__ void mma_fp16(float c[4], const uint32_t a[4],
                                         uint32_t b0, uint32_t b1) {
    asm volatile("mma.sync.aligned.m16n8k16.row.col.f32.f16.f16.f32 "
                 "{%0,%1,%2,%3}, {%4,%5,%6,%7}, {%8,%9}, {%0,%1,%2,%3};"
                 : "+f"(c[0]), "+f"(c[1]), "+f"(c[2]), "+f"(c[3])
                 : "r"(a[0]), "r"(a[1]), "r"(a[2]), "r"(a[3]),
                   "r"(b0), "r"(b1));
}

__device__ __forceinline__ uint32_t packh(float a, float b) {
    __half2 h = __floats2half2_rn(a, b);
    return *reinterpret_cast<uint32_t*>(&h);
}

// cp.async 16B, zero-fill when invalid
__device__ __forceinline__ void cp16(uint32_t dst, const void* src, int bytes) {
    asm volatile("cp.async.cg.shared.global [%0], [%1], 16, %2;"
                 :: "r"(dst), "l"(src), "r"(bytes));
}
#define CP_COMMIT() asm volatile("cp.async.commit_group;" ::: "memory")
#define CP_WAIT(n)  asm volatile("cp.async.wait_group %0;" :: "n"(n) : "memory")

// ---------------------------------------------------------------------------
__global__ void zero_kernel(float* __restrict__ out, int n) {
    int i = blockIdx.x * blockDim.x + threadIdx.x;
    if (i < n) out[i] = 0.0f;
    if (blockIdx.x == 0 && threadIdx.x < E_) g_cnt[threadIdx.x] = 0;
}

// ---------------------------------------------------------------------------
__global__ void conv_w_kernel(const float* __restrict__ w1,
                              const float* __restrict__ w2) {
    size_t i = ((size_t)blockIdx.x * blockDim.x + threadIdx.x) * 4;
    const float* src;
    __half* dst;
    if (i < (size_t)NW) { src = w1 + i;        dst = g_w1h + i; }
    else                { src = w2 + (i - NW); dst = g_w2h + (i - NW); }
    float4 v = *(const float4*)src;
    *(uint32_t*)dst       = packh(v.x, v.y);
    *(uint32_t*)(dst + 2) = packh(v.z, v.w);
}

__global__ void conv_x_kernel(const float* __restrict__ x) {
    int i = (blockIdx.x * blockDim.x + threadIdx.x) * 4;
    float4 v = *(const float4*)(x + i);
    *(uint32_t*)(g_xh + i)     = packh(v.x, v.y);
    *(uint32_t*)(g_xh + i + 2) = packh(v.z, v.w);
}

// ---------------------------------------------------------------------------
__global__ void router_kernel(const float* __restrict__ x,
                              const float* __restrict__ rw,
                              float* __restrict__ out, int out_size) {
    const int t = blockIdx.x;
    __shared__ float xs[D_];
    __shared__ float logits[E_];

    for (int i = threadIdx.x; i < D_; i += blockDim.x)
        xs[i] = x[(size_t)t * D_ + i];
    __syncthreads();

    const int w = threadIdx.x >> 5;
    const int lane = threadIdx.x & 31;
    float s = 0.0f;
    const float* rwe = rw + (size_t)w * D_;
    for (int k = lane; k < D_; k += 32) s += xs[k] * rwe[k];
    #pragma unroll
    for (int o = 16; o; o >>= 1) s += __shfl_xor_sync(0xffffffffu, s, o);
    if (lane == 0) logits[w] = s;
    __syncthreads();

    if (threadIdx.x == 0) {
        float mx = logits[0];
        #pragma unroll
        for (int e = 1; e < E_; e++) mx = fmaxf(mx, logits[e]);
        float p[E_]; float sum = 0.0f;
        #pragma unroll
        for (int e = 0; e < E_; e++) { p[e] = expf(logits[e] - mx); sum += p[e]; }
        float inv = 1.0f / sum;
        #pragma unroll
        for (int e = 0; e < E_; e++) p[e] *= inv;

        int i0 = 0;
        #pragma unroll
        for (int e = 1; e < E_; e++) if (p[e] > p[i0]) i0 = e;
        int i1 = (i0 == 0) ? 1 : 0;
        #pragma unroll
        for (int e = 0; e < E_; e++) if (e != i0 && p[e] > p[i1]) i1 = e;

        float w0 = p[i0], w1 = p[i1];
        float rinv = 1.0f / (w0 + w1);
        w0 *= rinv; w1 *= rinv;

        int s0 = atomicAdd(&g_cnt[i0], 1);
        g_tok[i0 * T_ + s0] = t; g_wt[i0 * T_ + s0] = w0;
        int s1 = atomicAdd(&g_cnt[i1], 1);
        g_tok[i1 * T_ + s1] = t; g_wt[i1 * T_ + s1] = w1;

        if (out_size >= OUT_FULL) {
            float* probs = out + OUT_MAIN;
            float* idxs  = out + OUT_MAIN + T_ * E_;
            float* wts   = out + OUT_MAIN + T_ * E_ + T_ * KTOP;
            #pragma unroll
            for (int e = 0; e < E_; e++) probs[t * E_ + e] = p[e];
            idxs[t * KTOP + 0] = (float)i0;
            idxs[t * KTOP + 1] = (float)i1;
            wts [t * KTOP + 0] = w0;
            wts [t * KTOP + 1] = w1;
        }
    }
}

// ---------------------------------------------------------------------------
// one pipeline stage's MMA phase: warp tile 32x64 (mi 0..1, nj 0..3)
// ---------------------------------------------------------------------------
__device__ __forceinline__ void mma_stage(uint32_t base, int a_r, int a_c,
                                          int b_r, int b_c,
                                          float acc[2][8][4]) {
    #pragma unroll
    for (int ks = 0; ks < 4; ks++) {
        uint32_t ah[2][4], bh[4][4];
        #pragma unroll
        for (int mi = 0; mi < 2; mi++)
            ldsm_x4(base + AA_OFF + swz(a_r + mi * 16, ks * 2 + a_c), ah[mi]);
        #pragma unroll
        for (int nj = 0; nj < 4; nj++)
            ldsm_x4(base + BB_OFF + swz(b_r + nj * 16, ks * 2 + b_c), bh[nj]);
        #pragma unroll
        for (int mi = 0; mi < 2; mi++)
            #pragma unroll
            for (int nj = 0; nj < 4; nj++)
                #pragma unroll
                for (int h = 0; h < 2; h++)
                    mma_fp16(acc[mi][nj*2+h], ah[mi], bh[nj][h*2], bh[nj][h*2+1]);
    }
}

// ---------------------------------------------------------------------------
// GEMM1: H[s,n] = silu( X[tok(s),:] . W1[e,n,:] ), H stored fp16
// ---------------------------------------------------------------------------
__global__ void __launch_bounds__(512, 1)
expert_gemm1_mma() {
    extern __shared__ char smem[];
    const int e = blockIdx.z;
    const int n_e = g_cnt[e];
    const int row0 = blockIdx.y * BM;
    if (row0 >= n_e) return;
    const int col0 = blockIdx.x * BN;
    const int tid = threadIdx.x, wid = tid >> 5, lane = tid & 31;

    int* toks = (int*)smem;
    if (tid < BM) {
        int r = row0 + tid;
        toks[tid] = (r < n_e) ? g_tok[e * T_ + r] : -1;
    }
    __syncthreads();
    const uint32_t sb = smem_u32(smem);

    // loader: 6 x 16B chunks per thread per stage (A: 2, B: 4)
    const __half* asrc[2]; uint32_t aoff[2]; int abytes[2];
    #pragma unroll
    for (int j = 0; j < 2; j++) {
        int c = tid + j * 512;          // 0..1023
        int row = c >> 3, kc = c & 7;
        int tok = toks[row];
        abytes[j] = (tok >= 0) ? 16 : 0;
        asrc[j] = g_xh + (size_t)(tok < 0 ? 0 : tok) * D_ + kc * 8;
        aoff[j] = AA_OFF + swz(row, kc);
    }
    const __half* bsrc[4]; uint32_t boff[4];
    const __half* wbase = g_w1h + (size_t)e * FF_ * D_;
    #pragma unroll
    for (int j = 0; j < 4; j++) {
        int c = tid + j * 512;          // 0..2047
        int row = c >> 3, kc = c & 7;
        bsrc[j] = wbase + (size_t)(col0 + row) * D_ + kc * 8;
        boff[j] = BB_OFF + swz(row, kc);
    }

    // mma role: 4x4 warp grid, warp tile 32x64
    const int warp_m = wid & 3, warp_n = wid >> 2;
    const int a_r = warp_m * 32 + (lane & 15);
    const int a_c = lane >> 4;
    const int b_r = warp_n * 64 + (lane & 7) + ((lane >> 4) & 1) * 8;
    const int b_c = (lane >> 3) & 1;

    float acc[2][8][4] = {};

    const int S = D_ / BK;   // 16
    // prologue: stages 0,1
    #pragma unroll
    for (int ps = 0; ps < 2; ps++) {
        uint32_t base = sb + SOFF_BUF + ps * STAGE;
        #pragma unroll
        for (int j = 0; j < 2; j++) cp16(base + aoff[j], asrc[j] + ps * BK, abytes[j]);
        #pragma unroll
        for (int j = 0; j < 4; j++) cp16(base + boff[j], bsrc[j] + ps * BK, 16);
        CP_COMMIT();
    }

    #pragma unroll 1
    for (int s = 0; s < S; s++) {
        if (s + 1 < S) { CP_WAIT(1); } else { CP_WAIT(0); }
        __syncthreads();
        if (s + 2 < S) {
            uint32_t base = sb + SOFF_BUF + ((s + 2) % NSTAGE) * STAGE;
            #pragma unroll
            for (int j = 0; j < 2; j++) cp16(base + aoff[j], asrc[j] + (s+2) * BK, abytes[j]);
            #pragma unroll
            for (int j = 0; j < 4; j++) cp16(base + boff[j], bsrc[j] + (s+2) * BK, 16);
            CP_COMMIT();
        }
        mma_stage(sb + SOFF_BUF + (s % NSTAGE) * STAGE, a_r, a_c, b_r, b_c, acc);
    }

    // epilogue: silu -> fp16 -> g_hh
    const int g = lane >> 2, tq = lane & 3;
    #pragma unroll
    for (int mi = 0; mi < 2; mi++) {
        const int rA = row0 + warp_m * 32 + mi * 16 + g;
        const int rB = rA + 8;
        #pragma unroll
        for (int u = 0; u < 8; u++) {
            const int col = col0 + warp_n * 64 + u * 8 + tq * 2;
            if (rA < n_e) {
                float a = acc[mi][u][0], b = acc[mi][u][1];
                a = a / (1.0f + __expf(-a));
                b = b / (1.0f + __expf(-b));
                *(uint32_t*)(g_hh + ((size_t)e * T_ + rA) * FF_ + col) = packh(a, b);
            }
            if (rB < n_e) {
                float a = acc[mi][u][2], b = acc[mi][u][3];
                a = a / (1.0f + __expf(-a));
                b = b / (1.0f + __expf(-b));
                *(uint32_t*)(g_hh + ((size_t)e * T_ + rB) * FF_ + col) = packh(a, b);
            }
        }
    }
}

// ---------------------------------------------------------------------------
// GEMM2: out[tok(s),n] += wt(s) * ( H[s,:] . W2[e,n,:] )
// ---------------------------------------------------------------------------
__global__ void __launch_bounds__(512, 1)
expert_gemm2_mma(float* __restrict__ out) {
    extern __shared__ char smem[];
    const int e = blockIdx.z;
    const int n_e = g_cnt[e];
    const int row0 = blockIdx.y * BM;
    if (row0 >= n_e) return;
    const int col0 = blockIdx.x * BN;
    const int tid = threadIdx.x, wid = tid >> 5, lane = tid & 31;

    int*   toks = (int*)smem;
    float* wts  = (float*)(smem + 512);
    if (tid < BM) {
        int r = row0 + tid;
        if (r < n_e) { toks[tid] = g_tok[e * T_ + r]; wts[tid] = g_wt[e * T_ + r]; }
        else         { toks[tid] = 0;                 wts[tid] = 0.0f; }
    }
    __syncthreads();
    const uint32_t sb = smem_u32(smem);

    // loader
    const __half* asrc[2]; uint32_t aoff[2];
    #pragma unroll
    for (int j = 0; j < 2; j++) {
        int c = tid + j * 512;
        int row = c >> 3, kc = c & 7;
        asrc[j] = g_hh + ((size_t)e * T_ + row0 + row) * FF_ + kc * 8;
        aoff[j] = AA_OFF + swz(row, kc);
    }
    const __half* bsrc[4]; uint32_t boff[4];
    const __half* wbase = g_w2h + (size_t)e * D_ * FF_;
    #pragma unroll
    for (int j = 0; j < 4; j++) {
        int c = tid + j * 512;
        int row = c >> 3, kc = c & 7;
        bsrc[j] = wbase + (size_t)(col0 + row) * FF_ + kc * 8;
        boff[j] = BB_OFF + swz(row, kc);
    }

    // mma role
    const int warp_m = wid & 3, warp_n = wid >> 2;
    const int a_r = warp_m * 32 + (lane & 15);
    const int a_c = lane >> 4;
    const int b_r = warp_n * 64 + (lane & 7) + ((lane >> 4) & 1) * 8;
    const int b_c = (lane >> 3) & 1;

    float acc[2][8][4] = {};

    const int S = FF_ / BK;   // 32
    #pragma unroll
    for (int ps = 0; ps < 2; ps++) {
        uint32_t base = sb + SOFF_BUF + ps * STAGE;
        #pragma unroll
        for (int j = 0; j < 2; j++) cp16(base + aoff[j], asrc[j] + ps * BK, 16);
        #pragma unroll
        for (int j = 0; j < 4; j++) cp16(base + boff[j], bsrc[j] + ps * BK, 16);
        CP_COMMIT();
    }

    #pragma unroll 1
    for (int s = 0; s < S; s++) {
        if (s + 1 < S) { CP_WAIT(1); } else { CP_WAIT(0); }
        __syncthreads();
        if (s + 2 < S) {
            uint32_t base = sb + SOFF_BUF + ((s + 2) % NSTAGE) * STAGE;
            #pragma unroll
            for (int j = 0; j < 2; j++) cp16(base + aoff[j], asrc[j] + (s+2) * BK, 16);
            #pragma unroll
            for (int j = 0; j < 4; j++) cp16(base + boff[j], bsrc[j] + (s+2) * BK, 16);
            CP_COMMIT();
        }
        mma_stage(sb + SOFF_BUF + (s % NSTAGE) * STAGE, a_r, a_c, b_r, b_c, acc);
    }

    // epilogue: weighted atomic scatter
    const int g = lane >> 2, tq = lane & 3;
    #pragma unroll
    for (int mi = 0; mi < 2; mi++) {
        const int rlA = warp_m * 32 + mi * 16 + g;
        const int rlB = rlA + 8;
        #pragma unroll
        for (int u = 0; u < 8; u++) {
            const int col = col0 + warp_n * 64 + u * 8 + tq * 2;
            if (row0 + rlA < n_e) {
                float w = wts[rlA];
                float* o = out + (size_t)toks[rlA] * D_ + col;
                atomicAdd(o,     w * acc[mi][u][0]);
                atomicAdd(o + 1, w * acc[mi][u][1]);
            }
            if (row0 + rlB < n_e) {
                float w = wts[rlB];
                float* o = out + (size_t)toks[rlB] * D_ + col;
                atomicAdd(o,     w * acc[mi][u][2]);
                atomicAdd(o + 1, w * acc[mi][u][3]);
            }
        }
    }
}

// ---------------------------------------------------------------------------
extern "C" void kernel_launch(void* const* d_in, const int* in_sizes, int n_in,
                              void* d_out, int out_size) {
    const float* x  = (const float*)d_in[0];
    const float* rw = (const float*)d_in[1];
    const float* w1 = (const float*)d_in[2];
    const float* w2 = (const float*)d_in[3];
    float* out = (float*)d_out;

    cudaFuncSetAttribute(expert_gemm1_mma,
                         cudaFuncAttributeMaxDynamicSharedMemorySize, SMEM_TOTAL);
    cudaFuncSetAttribute(expert_gemm2_mma,
                         cudaFuncAttributeMaxDynamicSharedMemorySize, SMEM_TOTAL);

    zero_kernel<<<(out_size + 255) / 256, 256>>>(out, out_size);
    conv_w_kernel<<<(2 * NW / 4) / 256, 256>>>(w1, w2);
    conv_x_kernel<<<(T_ * D_ / 4) / 256, 256>>>(x);
    router_kernel<<<T_, 256>>>(x, rw, out, out_size);
    expert_gemm1_mma<<<dim3(FF_ / BN, T_ / BM, E_), 512, SMEM_TOTAL>>>();
    expert_gemm2_mma<<<dim3(D_ / BN, T_ / BM, E_), 512, SMEM_TOTAL>>>(out);
}

// round 11
// speedup vs baseline: 2.3421x; 1.0525x over previous
#include <cuda_runtime.h>
#include <cuda_fp16.h>
#include <math.h>
#include <stdint.h>

// Problem constants
#define B_   2
#define S_   1024
#define D_   1024
#define E_   8
#define KTOP 2
#define FF_  2048
#define T_   (B_ * S_)
#define OUT_MAIN (T_ * D_)
#define OUT_FULL (OUT_MAIN + T_*E_ + T_*KTOP + T_*KTOP)
#define NW   (E_ * FF_ * D_)
#define CONV_BLOCKS ((2 * NW / 4) / 256)   // 32768

// GEMM tiling: 128x256x64 stages, 512 threads / 16 warps (4x4), warp tile 32x64
#define BM 128
#define BN 256
#define BK 64
#define AA_OFF 0
#define BB_OFF 16384
#define STAGE  49152
#define NSTAGE 3
#define SOFF_BUF 1024
#define SMEM_TOTAL (SOFF_BUF + NSTAGE * STAGE)   // 148480

// Device scratch
__device__ int   g_cnt[E_];
__device__ int   g_tok[E_ * T_];
__device__ float g_wt [E_ * T_];
__device__ __half g_w1h[(size_t)NW];
__device__ __half g_w2h[(size_t)NW];
__device__ __half g_xh[(size_t)T_ * D_];
__device__ __half g_hh[(size_t)E_ * T_ * FF_];

// ---------------------------------------------------------------------------
__device__ __forceinline__ uint32_t smem_u32(const void* p) {
    uint32_t a;
    asm("{ .reg .u64 t; cvta.to.shared.u64 t, %1; cvt.u32.u64 %0, t; }"
        : "=r"(a) : "l"(p));
    return a;
}

__device__ __forceinline__ uint32_t swz(int r, int c) {
    return (uint32_t)(r * 128 + ((c ^ (r & 7)) << 4));
}

__device__ __forceinline__ void ldsm_x4(uint32_t addr, uint32_t r[4]) {
    asm volatile("ldmatrix.sync.aligned.m8n8.x4.shared.b16 {%0,%1,%2,%3}, [%4];"
                 : "=r"(r[0]), "=r"(r[1]), "=r"(r[2]), "=r"(r[3]) : "r"(addr));
}

__device__ __forceinline__ void mma_fp16(float c[4], const uint32_t a[4],
                                         uint32_t b0, uint32_t b1) {
    asm volatile("mma.sync.aligned.m16n8k16.row.col.f32.f16.f16.f32 "
                 "{%0,%1,%2,%3}, {%4,%5,%6,%7}, {%8,%9}, {%0,%1,%2,%3};"
                 : "+f"(c[0]), "+f"(c[1]), "+f"(c[2]), "+f"(c[3])
                 : "r"(a[0]), "r"(a[1]), "r"(a[2]), "r"(a[3]),
                   "r"(b0), "r"(b1));
}

__device__ __forceinline__ uint32_t packh(float a, float b) {
    __half2 h = __floats2half2_rn(a, b);
    return *reinterpret_cast<uint32_t*>(&h);
}

__device__ __forceinline__ void cp16(uint32_t dst, const void* src, int bytes) {
    asm volatile("cp.async.cg.shared.global [%0], [%1], 16, %2;"
                 :: "r"(dst), "l"(src), "r"(bytes));
}
#define CP_COMMIT() asm volatile("cp.async.commit_group;" ::: "memory")
#define CP_WAIT(n)  asm volatile("cp.async.wait_group %0;" :: "n"(n) : "memory")

// ---------------------------------------------------------------------------
__global__ void zero_kernel(float* __restrict__ out, int n) {
    int i = blockIdx.x * blockDim.x + threadIdx.x;
    if (i < n) out[i] = 0.0f;
    if (blockIdx.x == 0 && threadIdx.x < E_) g_cnt[threadIdx.x] = 0;
}

// ---------------------------------------------------------------------------
// prep: blocks [0, T_) = router (+ fused x->fp16); blocks [T_, T_+CONV_BLOCKS)
// = fp32->fp16 weight conversion (w1 then w2). Single kernel => DRAM-bound
// conversion overlaps router's compute on other SMs, single-stream capture-safe.
// ---------------------------------------------------------------------------
__global__ void prep_kernel(const float* __restrict__ x,
                            const float* __restrict__ rw,
                            const float* __restrict__ w1,
                            const float* __restrict__ w2,
                            float* __restrict__ out, int out_size) {
    if (blockIdx.x >= T_) {
        // weight conversion path
        size_t i = ((size_t)(blockIdx.x - T_) * blockDim.x + threadIdx.x) * 4;
        const float* src;
        __half* dst;
        if (i < (size_t)NW) { src = w1 + i;        dst = g_w1h + i; }
        else                { src = w2 + (i - NW); dst = g_w2h + (i - NW); }
        float4 v = *(const float4*)src;
        *(uint32_t*)dst       = packh(v.x, v.y);
        *(uint32_t*)(dst + 2) = packh(v.z, v.w);
        return;
    }

    const int t = blockIdx.x;
    __shared__ float xs[D_];
    __shared__ float logits[E_];

    for (int i = threadIdx.x; i < D_; i += blockDim.x)
        xs[i] = x[(size_t)t * D_ + i];
    __syncthreads();

    // fused conv_x
    {
        int i0 = threadIdx.x * 4;
        *(uint32_t*)(g_xh + (size_t)t * D_ + i0)     = packh(xs[i0],     xs[i0 + 1]);
        *(uint32_t*)(g_xh + (size_t)t * D_ + i0 + 2) = packh(xs[i0 + 2], xs[i0 + 3]);
    }

    const int w = threadIdx.x >> 5;
    const int lane = threadIdx.x & 31;
    float s = 0.0f;
    const float* rwe = rw + (size_t)w * D_;
    for (int k = lane; k < D_; k += 32) s += xs[k] * rwe[k];
    #pragma unroll
    for (int o = 16; o; o >>= 1) s += __shfl_xor_sync(0xffffffffu, s, o);
    if (lane == 0) logits[w] = s;
    __syncthreads();

    if (threadIdx.x == 0) {
        float mx = logits[0];
        #pragma unroll
        for (int e = 1; e < E_; e++) mx = fmaxf(mx, logits[e]);
        float p[E_]; float sum = 0.0f;
        #pragma unroll
        for (int e = 0; e < E_; e++) { p[e] = expf(logits[e] - mx); sum += p[e]; }
        float inv = 1.0f / sum;
        #pragma unroll
        for (int e = 0; e < E_; e++) p[e] *= inv;

        int i0 = 0;
        #pragma unroll
        for (int e = 1; e < E_; e++) if (p[e] > p[i0]) i0 = e;
        int i1 = (i0 == 0) ? 1 : 0;
        #pragma unroll
        for (int e = 0; e < E_; e++) if (e != i0 && p[e] > p[i1]) i1 = e;

        float w0 = p[i0], w1v = p[i1];
        float rinv = 1.0f / (w0 + w1v);
        w0 *= rinv; w1v *= rinv;

        int s0 = atomicAdd(&g_cnt[i0], 1);
        g_tok[i0 * T_ + s0] = t; g_wt[i0 * T_ + s0] = w0;
        int s1 = atomicAdd(&g_cnt[i1], 1);
        g_tok[i1 * T_ + s1] = t; g_wt[i1 * T_ + s1] = w1v;

        if (out_size >= OUT_FULL) {
            float* probs = out + OUT_MAIN;
            float* idxs  = out + OUT_MAIN + T_ * E_;
            float* wts   = out + OUT_MAIN + T_ * E_ + T_ * KTOP;
            #pragma unroll
            for (int e = 0; e < E_; e++) probs[t * E_ + e] = p[e];
            idxs[t * KTOP + 0] = (float)i0;
            idxs[t * KTOP + 1] = (float)i1;
            wts [t * KTOP + 0] = w0;
            wts [t * KTOP + 1] = w1v;
        }
    }
}

// ---------------------------------------------------------------------------
__device__ __forceinline__ void mma_stage(uint32_t base, int a_r, int a_c,
                                          int b_r, int b_c,
                                          float acc[2][8][4]) {
    #pragma unroll
    for (int ks = 0; ks < 4; ks++) {
        uint32_t ah[2][4], bh[4][4];
        #pragma unroll
        for (int mi = 0; mi < 2; mi++)
            ldsm_x4(base + AA_OFF + swz(a_r + mi * 16, ks * 2 + a_c), ah[mi]);
        #pragma unroll
        for (int nj = 0; nj < 4; nj++)
            ldsm_x4(base + BB_OFF + swz(b_r + nj * 16, ks * 2 + b_c), bh[nj]);
        #pragma unroll
        for (int mi = 0; mi < 2; mi++)
            #pragma unroll
            for (int nj = 0; nj < 4; nj++)
                #pragma unroll
                for (int h = 0; h < 2; h++)
                    mma_fp16(acc[mi][nj*2+h], ah[mi], bh[nj][h*2], bh[nj][h*2+1]);
    }
}

// ---------------------------------------------------------------------------
__global__ void __launch_bounds__(512, 1)
expert_gemm1_mma() {
    extern __shared__ char smem[];
    const int e = blockIdx.z;
    const int n_e = g_cnt[e];
    const int row0 = blockIdx.y * BM;
    if (row0 >= n_e) return;
    const int col0 = blockIdx.x * BN;
    const int tid = threadIdx.x, wid = tid >> 5, lane = tid & 31;

    int* toks = (int*)smem;
    if (tid < BM) {
        int r = row0 + tid;
        toks[tid] = (r < n_e) ? g_tok[e * T_ + r] : -1;
    }
    __syncthreads();
    const uint32_t sb = smem_u32(smem);

    const __half* asrc[2]; uint32_t aoff[2]; int abytes[2];
    #pragma unroll
    for (int j = 0; j < 2; j++) {
        int c = tid + j * 512;
        int row = c >> 3, kc = c & 7;
        int tok = toks[row];
        abytes[j] = (tok >= 0) ? 16 : 0;
        asrc[j] = g_xh + (size_t)(tok < 0 ? 0 : tok) * D_ + kc * 8;
        aoff[j] = AA_OFF + swz(row, kc);
    }
    const __half* bsrc[4]; uint32_t boff[4];
    const __half* wbase = g_w1h + (size_t)e * FF_ * D_;
    #pragma unroll
    for (int j = 0; j < 4; j++) {
        int c = tid + j * 512;
        int row = c >> 3, kc = c & 7;
        bsrc[j] = wbase + (size_t)(col0 + row) * D_ + kc * 8;
        boff[j] = BB_OFF + swz(row, kc);
    }

    const int warp_m = wid & 3, warp_n = wid >> 2;
    const int a_r = warp_m * 32 + (lane & 15);
    const int a_c = lane >> 4;
    const int b_r = warp_n * 64 + (lane & 7) + ((lane >> 4) & 1) * 8;
    const int b_c = (lane >> 3) & 1;

    float acc[2][8][4] = {};

    const int S = D_ / BK;
    #pragma unroll
    for (int ps = 0; ps < 2; ps++) {
        uint32_t base = sb + SOFF_BUF + ps * STAGE;
        #pragma unroll
        for (int j = 0; j < 2; j++) cp16(base + aoff[j], asrc[j] + ps * BK, abytes[j]);
        #pragma unroll
        for (int j = 0; j < 4; j++) cp16(base + boff[j], bsrc[j] + ps * BK, 16);
        CP_COMMIT();
    }

    #pragma unroll 1
    for (int s = 0; s < S; s++) {
        if (s + 1 < S) { CP_WAIT(1); } else { CP_WAIT(0); }
        __syncthreads();
        if (s + 2 < S) {
            uint32_t base = sb + SOFF_BUF + ((s + 2) % NSTAGE) * STAGE;
            #pragma unroll
            for (int j = 0; j < 2; j++) cp16(base + aoff[j], asrc[j] + (s+2) * BK, abytes[j]);
            #pragma unroll
            for (int j = 0; j < 4; j++) cp16(base + boff[j], bsrc[j] + (s+2) * BK, 16);
            CP_COMMIT();
        }
        mma_stage(sb + SOFF_BUF + (s % NSTAGE) * STAGE, a_r, a_c, b_r, b_c, acc);
    }

    const int g = lane >> 2, tq = lane & 3;
    #pragma unroll
    for (int mi = 0; mi < 2; mi++) {
        const int rA = row0 + warp_m * 32 + mi * 16 + g;
        const int rB = rA + 8;
        #pragma unroll
        for (int u = 0; u < 8; u++) {
            const int col = col0 + warp_n * 64 + u * 8 + tq * 2;
            if (rA < n_e) {
                float a = acc[mi][u][0], b = acc[mi][u][1];
                a = a / (1.0f + __expf(-a));
                b = b / (1.0f + __expf(-b));
                *(uint32_t*)(g_hh + ((size_t)e * T_ + rA) * FF_ + col) = packh(a, b);
            }
            if (rB < n_e) {
                float a = acc[mi][u][2], b = acc[mi][u][3];
                a = a / (1.0f + __expf(-a));
                b = b / (1.0f + __expf(-b));
                *(uint32_t*)(g_hh + ((size_t)e * T_ + rB) * FF_ + col) = packh(a, b);
            }
        }
    }
}

// ---------------------------------------------------------------------------
__global__ void __launch_bounds__(512, 1)
expert_gemm2_mma(float* __restrict__ out) {
    extern __shared__ char smem[];
    const int e = blockIdx.z;
    const int n_e = g_cnt[e];
    const int row0 = blockIdx.y * BM;
    if (row0 >= n_e) return;
    const int col0 = blockIdx.x * BN;
    const int tid = threadIdx.x, wid = tid >> 5, lane = tid & 31;

    int*   toks = (int*)smem;
    float* wts  = (float*)(smem + 512);
    if (tid < BM) {
        int r = row0 + tid;
        if (r < n_e) { toks[tid] = g_tok[e * T_ + r]; wts[tid] = g_wt[e * T_ + r]; }
        else         { toks[tid] = 0;                 wts[tid] = 0.0f; }
    }
    __syncthreads();
    const uint32_t sb = smem_u32(smem);

    const __half* asrc[2]; uint32_t aoff[2];
    #pragma unroll
    for (int j = 0; j < 2; j++) {
        int c = tid + j * 512;
        int row = c >> 3, kc = c & 7;
        asrc[j] = g_hh + ((size_t)e * T_ + row0 + row) * FF_ + kc * 8;
        aoff[j] = AA_OFF + swz(row, kc);
    }
    const __half* bsrc[4]; uint32_t boff[4];
    const __half* wbase = g_w2h + (size_t)e * D_ * FF_;
    #pragma unroll
    for (int j = 0; j < 4; j++) {
        int c = tid + j * 512;
        int row = c >> 3, kc = c & 7;
        bsrc[j] = wbase + (size_t)(col0 + row) * FF_ + kc * 8;
        boff[j] = BB_OFF + swz(row, kc);
    }

    const int warp_m = wid & 3, warp_n = wid >> 2;
    const int a_r = warp_m * 32 + (lane & 15);
    const int a_c = lane >> 4;
    const int b_r = warp_n * 64 + (lane & 7) + ((lane >> 4) & 1) * 8;
    const int b_c = (lane >> 3) & 1;

    float acc[2][8][4] = {};

    const int S = FF_ / BK;
    #pragma unroll
    for (int ps = 0; ps < 2; ps++) {
        uint32_t base = sb + SOFF_BUF + ps * STAGE;
        #pragma unroll
        for (int j = 0; j < 2; j++) cp16(base + aoff[j], asrc[j] + ps * BK, 16);
        #pragma unroll
        for (int j = 0; j < 4; j++) cp16(base + boff[j], bsrc[j] + ps * BK, 16);
        CP_COMMIT();
    }

    #pragma unroll 1
    for (int s = 0; s < S; s++) {
        if (s + 1 < S) { CP_WAIT(1); } else { CP_WAIT(0); }
        __syncthreads();
        if (s + 2 < S) {
            uint32_t base = sb + SOFF_BUF + ((s + 2) % NSTAGE) * STAGE;
            #pragma unroll
            for (int j = 0; j < 2; j++) cp16(base + aoff[j], asrc[j] + (s+2) * BK, 16);
            #pragma unroll
            for (int j = 0; j < 4; j++) cp16(base + boff[j], bsrc[j] + (s+2) * BK, 16);
            CP_COMMIT();
        }
        mma_stage(sb + SOFF_BUF + (s % NSTAGE) * STAGE, a_r, a_c, b_r, b_c, acc);
    }

    const int g = lane >> 2, tq = lane & 3;
    #pragma unroll
    for (int mi = 0; mi < 2; mi++) {
        const int rlA = warp_m * 32 + mi * 16 + g;
        const int rlB = rlA + 8;
        #pragma unroll
        for (int u = 0; u < 8; u++) {
            const int col = col0 + warp_n * 64 + u * 8 + tq * 2;
            if (row0 + rlA < n_e) {
                float w = wts[rlA];
                float* o = out + (size_t)toks[rlA] * D_ + col;
                atomicAdd(o,     w * acc[mi][u][0]);
                atomicAdd(o + 1, w * acc[mi][u][1]);
            }
            if (row0 + rlB < n_e) {
                float w = wts[rlB];
                float* o = out + (size_t)toks[rlB] * D_ + col;
                atomicAdd(o,     w * acc[mi][u][2]);
                atomicAdd(o + 1, w * acc[mi][u][3]);
            }
        }
    }
}

// ---------------------------------------------------------------------------
extern "C" void kernel_launch(void* const* d_in, const int* in_sizes, int n_in,
                              void* d_out, int out_size) {
    const float* x  = (const float*)d_in[0];
    const float* rw = (const float*)d_in[1];
    const float* w1 = (const float*)d_in[2];
    const float* w2 = (const float*)d_in[3];
    float* out = (float*)d_out;

    cudaFuncSetAttribute(expert_gemm1_mma,
                         cudaFuncAttributeMaxDynamicSharedMemorySize, SMEM_TOTAL);
    cudaFuncSetAttribute(expert_gemm2_mma,
                         cudaFuncAttributeMaxDynamicSharedMemorySize, SMEM_TOTAL);

    zero_kernel<<<(out_size + 255) / 256, 256>>>(out, out_size);
    prep_kernel<<<T_ + CONV_BLOCKS, 256>>>(x, rw, w1, w2, out, out_size);
    expert_gemm1_mma<<<dim3(FF_ / BN, T_ / BM, E_), 512, SMEM_TOTAL>>>();
    expert_gemm2_mma<<<dim3(D_ / BN, T_ / BM, E_), 512, SMEM_TOTAL>>>(out);
}